// round 9
// baseline (speedup 1.0000x reference)
#include <cuda_runtime.h>
#include <cstddef>
#include <cstdint>

// ---------------------------------------------------------------------------
// DA-RNN: B=512, T=64, I=128, H=128, E=127
// Round 8: MUFU-free tanh/sigmoid (FMA rational approx + Newton reciprocal).
// Theory: R7 was MUFU-roofline-bound (~1.2G MUFU ops ~= 9ms serialized).
// ---------------------------------------------------------------------------

#define B_  512
#define T_  64
#define I_  128
#define H_  128
#define E_  127
#define SN  (B_*H_)   // 65536

// ------------------------- device scratch (static) -------------------------
__device__ float g_state[8 * SN];
__device__ float g_P[(size_t)B_ * E_ * T_];
__device__ float g_hexp[(size_t)B_ * T_ * H_];
__device__ float g_Hproj[(size_t)B_ * T_ * H_];
__device__ float g_W1Te[320 * 64];
__device__ float g_W1Td[384 * 128];
__device__ float g_xs[B_ * E_];
__device__ float g_din[B_];
__device__ float g_partial[B_ * H_];

// ------------------------------ math helpers -------------------------------
// MUFU-free reciprocal for q > 0: bit-trick seed + 3 Newton steps (~4e-11 rel).
__device__ __forceinline__ float rcp_fast(float q) {
    float r = __uint_as_float(0x7EF311C3u - __float_as_uint(q));
    r = r * fmaf(-q, r, 2.0f);
    r = r * fmaf(-q, r, 2.0f);
    r = r * fmaf(-q, r, 2.0f);
    return r;
}

// FMA-only tanh: rational minimax (Eigen coefficients), clamp at 7.90531.
// abs error ~1e-7 vs true tanh. Zero MUFU ops.
__device__ __forceinline__ float tanh_fma(float x) {
    const float kClamp = 7.90531110763549805f;
    x = fminf(fmaxf(x, -kClamp), kClamp);
    float x2 = x * x;
    float p = -2.76076847742355e-16f;
    p = fmaf(p, x2, 2.00018790482477e-13f);
    p = fmaf(p, x2, -8.60467152213735e-11f);
    p = fmaf(p, x2, 5.12229709037114e-08f);
    p = fmaf(p, x2, 1.48572235717979e-05f);
    p = fmaf(p, x2, 6.37261928875436e-04f);
    p = fmaf(p, x2, 4.89352455891786e-03f);
    p = x * p;
    float q = 1.19825839466702e-06f;
    q = fmaf(q, x2, 1.18534705686654e-04f);
    q = fmaf(q, x2, 2.26843463243900e-03f);
    q = fmaf(q, x2, 4.89352518554385e-03f);
    return p * rcp_fast(q);
}

__device__ __forceinline__ float sig_fma(float x) {
    return fmaf(tanh_fma(0.5f * x), 0.5f, 0.5f);
}

// ------------------------------- utilities ---------------------------------
__global__ void darnn_zero_states(float* h0, float* c0, float* h1, float* c1) {
    int i = blockIdx.x * blockDim.x + threadIdx.x;
    if (i < SN) { h0[i] = 0.f; c0[i] = 0.f; h1[i] = 0.f; c1[i] = 0.f; }
}

__global__ void darnn_transpose(const float* __restrict__ src, float* __restrict__ dst,
                                int rows, int cols) {
    int idx = blockIdx.x * blockDim.x + threadIdx.x;
    if (idx < rows * cols) {
        int r = idx / cols, c = idx % cols;
        dst[c * rows + r] = src[idx];
    }
}

// ------------------ encoder attention pre-projection (once) ----------------
__global__ void darnn_penc(const float* __restrict__ input,
                           const float* __restrict__ W1T,
                           const float* __restrict__ b1,
                           float* __restrict__ P) {
    int row0 = blockIdx.x * 4;
    int tx = threadIdx.x;
    int j = tx & 63;
    int r = tx >> 6;
    int row = row0 + r;
    int b = row / E_;
    int e = row % E_;
    __shared__ float xsm[4][65];
    xsm[r][j] = input[((size_t)b * T_ + j) * I_ + 1 + e];
    __syncthreads();
    float acc = b1[j];
#pragma unroll 8
    for (int k = 0; k < 64; k++)
        acc += xsm[r][k] * W1T[(256 + k) * 64 + j];
    P[(size_t)row * 64 + j] = acc;
}

// ------------------ decoder attention pre-projection (once) ----------------
__global__ void darnn_hproj(const float* __restrict__ hexp,
                            const float* __restrict__ W1dT,
                            const float* __restrict__ b1d,
                            float* __restrict__ Hproj) {
    int row0 = blockIdx.x * 16;
    int tx = threadIdx.x;
    int j = tx & 127;
    int rs = tx >> 7;
    __shared__ float hs[16][129];
#pragma unroll
    for (int i = 0; i < 8; i++) {
        int r = (tx >> 7) + 2 * i;
        hs[r][tx & 127] = hexp[((size_t)row0 + r) * H_ + (tx & 127)];
    }
    __syncthreads();
    float acc[8];
#pragma unroll
    for (int i = 0; i < 8; i++) acc[i] = b1d[j];
    for (int k = 0; k < 128; k++) {
        float w = W1dT[(256 + k) * 128 + j];
#pragma unroll
        for (int i = 0; i < 8; i++) acc[i] += hs[rs + 2 * i][k] * w;
    }
#pragma unroll
    for (int i = 0; i < 8; i++)
        Hproj[((size_t)row0 + rs + 2 * i) * H_ + j] = acc[i];
}

// -------------------------- encoder attention step --------------------------
__global__ void darnn_enc_attn(const float* __restrict__ input,
                               const float* __restrict__ h1, const float* __restrict__ c1,
                               const float* __restrict__ W1T,
                               const float* __restrict__ W2,
                               const float* __restrict__ b2,
                               const float* __restrict__ P,
                               float* __restrict__ xs, int t) {
    int b = blockIdx.x;
    int tx = threadIdx.x;
    __shared__ float h1s[128], c1s[128], hvec[64], W2s[64], red[128];
    h1s[tx] = h1[b * H_ + tx];
    c1s[tx] = c1[b * H_ + tx];
    if (tx < 64) W2s[tx] = W2[tx];
    __syncthreads();
    if (tx < 64) {
        float acc = 0.f;
#pragma unroll 8
        for (int h = 0; h < 128; h++)
            acc += h1s[h] * W1T[h * 64 + tx] + c1s[h] * W1T[(128 + h) * 64 + tx];
        hvec[tx] = acc;
    }
    __syncthreads();
    float lg = -3.0e38f;
    if (tx < E_) {
        const float* Pr = P + ((size_t)b * E_ + tx) * 64;
        float acc = b2[0];
#pragma unroll 4
        for (int j = 0; j < 64; j++)
            acc += tanh_fma(Pr[j] + hvec[j]) * W2s[j];
        lg = acc;
    }
    red[tx] = lg;
    __syncthreads();
    for (int s = 64; s > 0; s >>= 1) { if (tx < s) red[tx] = fmaxf(red[tx], red[tx + s]); __syncthreads(); }
    float m = red[0];
    __syncthreads();
    float ex = (tx < E_) ? __expf(lg - m) : 0.f;
    red[tx] = ex;
    __syncthreads();
    for (int s = 64; s > 0; s >>= 1) { if (tx < s) red[tx] += red[tx + s]; __syncthreads(); }
    float inv = 1.0f / red[0];
    if (tx < E_)
        xs[b * E_ + tx] = input[((size_t)b * T_ + t) * I_ + 1 + tx] * ex * inv;
}

// -------------------------- decoder attention step --------------------------
__global__ void darnn_dec_attn(const float* __restrict__ input,
                               const float* __restrict__ h1, const float* __restrict__ c1,
                               const float* __restrict__ W1dT,
                               const float* __restrict__ W2d,
                               const float* __restrict__ b2d,
                               const float* __restrict__ Hproj,
                               const float* __restrict__ hexp,
                               const float* __restrict__ decinW,
                               const float* __restrict__ decinB,
                               float* __restrict__ din,
                               float* __restrict__ partial, int t) {
    int b = blockIdx.x;
    int tx = threadIdx.x;
    __shared__ float h1s[128], c1s[128], hvec[128], W2s[128], a_s[64], red[128];
    h1s[tx] = h1[b * H_ + tx];
    c1s[tx] = c1[b * H_ + tx];
    W2s[tx] = W2d[tx];
    __syncthreads();
    {
        float acc = 0.f;
#pragma unroll 8
        for (int h = 0; h < 128; h++)
            acc += h1s[h] * W1dT[h * 128 + tx] + c1s[h] * W1dT[(128 + h) * 128 + tx];
        hvec[tx] = acc;
    }
    __syncthreads();
    float lg = -3.0e38f;
    if (tx < T_) {
        const float* Pr = Hproj + ((size_t)b * T_ + tx) * 128;
        float acc = b2d[0];
#pragma unroll 4
        for (int j = 0; j < 128; j++)
            acc += tanh_fma(Pr[j] + hvec[j]) * W2s[j];
        lg = acc;
    }
    red[tx] = lg;
    __syncthreads();
    for (int s = 64; s > 0; s >>= 1) { if (tx < s) red[tx] = fmaxf(red[tx], red[tx + s]); __syncthreads(); }
    float m = red[0];
    __syncthreads();
    float ex = (tx < T_) ? __expf(lg - m) : 0.f;
    red[tx] = ex;
    __syncthreads();
    for (int s = 64; s > 0; s >>= 1) { if (tx < s) red[tx] += red[tx + s]; __syncthreads(); }
    float inv = 1.0f / red[0];
    if (tx < T_) a_s[tx] = ex * inv;
    __syncthreads();
    float p = 0.f;
#pragma unroll 8
    for (int tt = 0; tt < T_; tt++)
        p += a_s[tt] * hexp[((size_t)b * T_ + tt) * H_ + tx];
    partial[b * H_ + tx] = p;
    red[tx] = p * decinW[tx];
    __syncthreads();
    for (int s = 64; s > 0; s >>= 1) { if (tx < s) red[tx] += red[tx + s]; __syncthreads(); }
    if (tx == 0)
        din[b] = red[0] + decinW[128] * input[((size_t)b * T_ + t) * I_ + 0] + decinB[0];
}

// ------------------------------ fused LSTM cell -----------------------------
__global__ void darnn_lstm_cell(const float* __restrict__ X, int Kx,
                                const float* __restrict__ Wih,
                                const float* __restrict__ Hp,
                                const float* __restrict__ Whh,
                                const float* __restrict__ bih,
                                const float* __restrict__ bhh,
                                const float* __restrict__ Cp,
                                float* __restrict__ Hout,
                                float* __restrict__ Cout,
                                float* __restrict__ Hcopy, int hstride) {
    const int b0 = blockIdx.x * 16;
    const int h0 = blockIdx.y * 32;
    const int tx = threadIdx.x;
    const int hp = tx & 15;
    const int bg = tx >> 4;
    const int lane = tx & 31;
    const int rgrp = tx >> 5;

    __shared__ float As[16][33];
    __shared__ float Bs[32][129];

    float acc[2][2][4];
#pragma unroll
    for (int a = 0; a < 2; a++)
#pragma unroll
        for (int c = 0; c < 2; c++)
#pragma unroll
            for (int g = 0; g < 4; g++) acc[a][c][g] = 0.f;

    for (int phase = 0; phase < 2; phase++) {
        const float* Ag = phase ? Hp : X;
        const float* Bg = phase ? Whh : Wih;
        const int K = phase ? H_ : Kx;
        const int ntiles = (K + 31) >> 5;
        for (int kt = 0; kt < ntiles; kt++) {
            const int kb = kt << 5;
            {
                int k = lane;
                int r0 = rgrp;
#pragma unroll
                for (int i = 0; i < 4; i++) {
                    int r = r0 + i * 4;
                    As[r][k] = (kb + k < K) ? Ag[(size_t)(b0 + r) * K + kb + k] : 0.f;
                }
            }
            {
                bool ok = (kb + lane) < K;
#pragma unroll
                for (int i = 0; i < 32; i++) {
                    int r = i * 4 + rgrp;
                    int g = r >> 5, hl = r & 31;
                    int j = g * H_ + h0 + hl;
                    Bs[lane][r] = ok ? Bg[(size_t)j * K + kb + lane] : 0.f;
                }
            }
            __syncthreads();
#pragma unroll
            for (int k = 0; k < 32; k++) {
                float a0 = As[2 * bg][k];
                float a1 = As[2 * bg + 1][k];
#pragma unroll
                for (int g = 0; g < 4; g++) {
                    float w0 = Bs[k][g * 32 + 2 * hp];
                    float w1 = Bs[k][g * 32 + 2 * hp + 1];
                    acc[0][0][g] += a0 * w0;
                    acc[0][1][g] += a0 * w1;
                    acc[1][0][g] += a1 * w0;
                    acc[1][1][g] += a1 * w1;
                }
            }
            __syncthreads();
        }
    }
#pragma unroll
    for (int bi = 0; bi < 2; bi++) {
        int b = b0 + 2 * bg + bi;
#pragma unroll
        for (int hi = 0; hi < 2; hi++) {
            int h = h0 + 2 * hp + hi;
            float gi = acc[bi][hi][0] + bih[h]         + bhh[h];
            float gf = acc[bi][hi][1] + bih[H_ + h]    + bhh[H_ + h];
            float gg = acc[bi][hi][2] + bih[2*H_ + h]  + bhh[2*H_ + h];
            float go = acc[bi][hi][3] + bih[3*H_ + h]  + bhh[3*H_ + h];
            float cp = Cp[b * H_ + h];
            float c2 = sig_fma(gf) * cp + sig_fma(gi) * tanh_fma(gg);
            float h2 = sig_fma(go) * tanh_fma(c2);
            Cout[b * H_ + h] = c2;
            Hout[b * H_ + h] = h2;
            if (Hcopy) Hcopy[(size_t)b * hstride + h] = h2;
        }
    }
}

// ------------------------------- final output -------------------------------
__global__ void darnn_final(const float* __restrict__ h1f,
                            const float* __restrict__ partial,
                            const float* __restrict__ projW,
                            const float* __restrict__ projB,
                            float* __restrict__ out) {
    int b = blockIdx.x * blockDim.x + threadIdx.x;
    if (b < B_) {
        float acc = projB[0];
#pragma unroll 8
        for (int h = 0; h < H_; h++)
            acc += h1f[b * H_ + h] * projW[h] + partial[b * H_ + h] * projW[H_ + h];
        out[b] = acc;
    }
}

// --------------------------------- launcher ---------------------------------
extern "C" void kernel_launch(void* const* d_in, const int* in_sizes, int n_in,
                              void* d_out, int out_size) {
    const float* input    = (const float*)d_in[0];
    const float* eWih0    = (const float*)d_in[1];
    const float* eWhh0    = (const float*)d_in[2];
    const float* ebih0    = (const float*)d_in[3];
    const float* ebhh0    = (const float*)d_in[4];
    const float* eWih1    = (const float*)d_in[5];
    const float* eWhh1    = (const float*)d_in[6];
    const float* ebih1    = (const float*)d_in[7];
    const float* ebhh1    = (const float*)d_in[8];
    const float* dWih0    = (const float*)d_in[9];
    const float* dWhh0    = (const float*)d_in[10];
    const float* dbih0    = (const float*)d_in[11];
    const float* dbhh0    = (const float*)d_in[12];
    const float* dWih1    = (const float*)d_in[13];
    const float* dWhh1    = (const float*)d_in[14];
    const float* dbih1    = (const float*)d_in[15];
    const float* dbhh1    = (const float*)d_in[16];
    const float* attnW1   = (const float*)d_in[17];
    const float* attnB1   = (const float*)d_in[18];
    const float* attnW2   = (const float*)d_in[19];
    const float* attnB2   = (const float*)d_in[20];
    const float* attndW1  = (const float*)d_in[21];
    const float* attndB1  = (const float*)d_in[22];
    const float* attndW2  = (const float*)d_in[23];
    const float* attndB2  = (const float*)d_in[24];
    const float* decinW   = (const float*)d_in[25];
    const float* decinB   = (const float*)d_in[26];
    const float* projW    = (const float*)d_in[27];
    const float* projB    = (const float*)d_in[28];
    (void)in_sizes; (void)n_in; (void)out_size;

    float *st, *P, *hexp, *Hproj, *W1Te, *W1Td, *xs, *din, *part;
    cudaGetSymbolAddress((void**)&st,    g_state);
    cudaGetSymbolAddress((void**)&P,     g_P);
    cudaGetSymbolAddress((void**)&hexp,  g_hexp);
    cudaGetSymbolAddress((void**)&Hproj, g_Hproj);
    cudaGetSymbolAddress((void**)&W1Te,  g_W1Te);
    cudaGetSymbolAddress((void**)&W1Td,  g_W1Td);
    cudaGetSymbolAddress((void**)&xs,    g_xs);
    cudaGetSymbolAddress((void**)&din,   g_din);
    cudaGetSymbolAddress((void**)&part,  g_partial);

    float* h0[2] = { st + 0 * SN, st + 1 * SN };
    float* c0[2] = { st + 2 * SN, st + 3 * SN };
    float* h1[2] = { st + 4 * SN, st + 5 * SN };
    float* c1[2] = { st + 6 * SN, st + 7 * SN };

    dim3 cellGrid(32, 4);

    darnn_transpose<<<80, 256>>>(attnW1, W1Te, 64, 320);
    darnn_transpose<<<192, 256>>>(attndW1, W1Td, 128, 384);
    darnn_penc<<<(B_ * E_) / 4, 256>>>(input, W1Te, attnB1, P);
    darnn_zero_states<<<256, 256>>>(h0[0], c0[0], h1[0], c1[0]);

    for (int t = 0; t < T_; t++) {
        int p = t & 1, q = p ^ 1;
        darnn_enc_attn<<<B_, 128>>>(input, h1[p], c1[p], W1Te, attnW2, attnB2, P, xs, t);
        darnn_lstm_cell<<<cellGrid, 128>>>(xs, E_, eWih0, h0[p], eWhh0, ebih0, ebhh0,
                                           c0[p], h0[q], c0[q], nullptr, 0);
        darnn_lstm_cell<<<cellGrid, 128>>>(h0[q], H_, eWih1, h1[p], eWhh1, ebih1, ebhh1,
                                           c1[p], h1[q], c1[q], hexp + (size_t)t * H_, T_ * H_);
    }

    darnn_hproj<<<(B_ * T_) / 16, 256>>>(hexp, W1Td, attndB1, Hproj);
    darnn_zero_states<<<256, 256>>>(h0[0], c0[0], h1[0], c1[0]);

    for (int t = 0; t < T_; t++) {
        int p = t & 1, q = p ^ 1;
        darnn_dec_attn<<<B_, 128>>>(input, h1[p], c1[p], W1Td, attndW2, attndB2,
                                    Hproj, hexp, decinW, decinB, din, part, t);
        darnn_lstm_cell<<<cellGrid, 128>>>(din, 1, dWih0, h0[p], dWhh0, dbih0, dbhh0,
                                           c0[p], h0[q], c0[q], nullptr, 0);
        darnn_lstm_cell<<<cellGrid, 128>>>(h0[q], H_, dWih1, h1[p], dWhh1, dbih1, dbhh1,
                                           c1[p], h1[q], c1[q], nullptr, 0);
    }

    darnn_final<<<4, 128>>>(h1[0], part, projW, projB, (float*)d_out);
}

// round 10
// speedup vs baseline: 1.1698x; 1.1698x over previous
#include <cuda_runtime.h>
#include <cstddef>
#include <cstdint>

// ---------------------------------------------------------------------------
// DA-RNN: B=512, T=64, I=128, H=128, E=127
// Round 9: coalesced attention (P2/Hproj2 transposed layouts) + leaner cell.
// R8 post-mortem: bottleneck = 32-way uncoalesced attention loads, not MUFU.
// ---------------------------------------------------------------------------

#define B_  512
#define T_  64
#define I_  128
#define H_  128
#define E_  127
#define SN  (B_*H_)   // 65536

// ------------------------- device scratch (static) -------------------------
__device__ float g_state[8 * SN];
__device__ float g_P[(size_t)B_ * E_ * T_];      // enc pre-proj (b,e,j)
__device__ float g_P2[(size_t)B_ * 64 * 128];    // enc pre-proj (b,j,e) coalesced
__device__ float g_hexp[(size_t)B_ * T_ * H_];   // (b,t,h)
__device__ float g_Hproj2[(size_t)B_ * 128 * 64];// dec pre-proj (b,j,t) coalesced
__device__ float g_W1Te[320 * 64];
__device__ float g_W1Td[384 * 128];
__device__ float g_xs[B_ * E_];
__device__ float g_din[B_];
__device__ float g_partial[B_ * H_];

// ------------------------------ math helpers -------------------------------
__device__ __forceinline__ float rcp_fast(float q) {
    float r = __uint_as_float(0x7EF311C3u - __float_as_uint(q));
    r = r * fmaf(-q, r, 2.0f);
    r = r * fmaf(-q, r, 2.0f);
    r = r * fmaf(-q, r, 2.0f);
    return r;
}
__device__ __forceinline__ float tanh_fma(float x) {
    const float kClamp = 7.90531110763549805f;
    x = fminf(fmaxf(x, -kClamp), kClamp);
    float x2 = x * x;
    float p = -2.76076847742355e-16f;
    p = fmaf(p, x2, 2.00018790482477e-13f);
    p = fmaf(p, x2, -8.60467152213735e-11f);
    p = fmaf(p, x2, 5.12229709037114e-08f);
    p = fmaf(p, x2, 1.48572235717979e-05f);
    p = fmaf(p, x2, 6.37261928875436e-04f);
    p = fmaf(p, x2, 4.89352455891786e-03f);
    p = x * p;
    float q = 1.19825839466702e-06f;
    q = fmaf(q, x2, 1.18534705686654e-04f);
    q = fmaf(q, x2, 2.26843463243900e-03f);
    q = fmaf(q, x2, 4.89352518554385e-03f);
    return p * rcp_fast(q);
}
__device__ __forceinline__ float sig_fma(float x) {
    return fmaf(tanh_fma(0.5f * x), 0.5f, 0.5f);
}

// ------------------------- prep: W transposes + zero -----------------------
__global__ void darnn_prep(const float* __restrict__ aW1, const float* __restrict__ adW1,
                           float* __restrict__ W1Te, float* __restrict__ W1Td,
                           float* h0, float* c0, float* h1, float* c1) {
    int i = blockIdx.x * blockDim.x + threadIdx.x;
    if (i < 64 * 320) { int r = i / 320, c = i % 320; W1Te[c * 64 + r] = aW1[i]; }
    if (i < 128 * 384) { int r = i / 384, c = i % 384; W1Td[c * 128 + r] = adW1[i]; }
    if (i < SN) { h0[i] = 0.f; c0[i] = 0.f; h1[i] = 0.f; c1[i] = 0.f; }
}

__global__ void darnn_zero_states(float* h0, float* c0, float* h1, float* c1) {
    int i = blockIdx.x * blockDim.x + threadIdx.x;
    if (i < SN) { h0[i] = 0.f; c0[i] = 0.f; h1[i] = 0.f; c1[i] = 0.f; }
}

// ------------------ encoder attention pre-projection (once) ----------------
// P[b,e,j] = b1[j] + sum_k input[b,k,e+1] * W1[j,256+k]
__global__ void darnn_penc(const float* __restrict__ input,
                           const float* __restrict__ W1T,
                           const float* __restrict__ b1,
                           float* __restrict__ P) {
    int row0 = blockIdx.x * 4;
    int tx = threadIdx.x;
    int j = tx & 63;
    int r = tx >> 6;
    int row = row0 + r;
    int b = row / E_;
    int e = row % E_;
    __shared__ float xsm[4][65];
    xsm[r][j] = input[((size_t)b * T_ + j) * I_ + 1 + e];
    __syncthreads();
    float acc = b1[j];
#pragma unroll 8
    for (int k = 0; k < 64; k++)
        acc += xsm[r][k] * W1T[(256 + k) * 64 + j];
    P[(size_t)row * 64 + j] = acc;
}

// -------- transpose P (b,e,j) -> P2 (b,j,e); coalesced both directions -----
__global__ void darnn_ptrans(const float* __restrict__ P, float* __restrict__ P2) {
    int bb = blockIdx.x >> 1;
    int j0 = (blockIdx.x & 1) * 32;
    __shared__ float sm[128][33];
    int tx = threadIdx.x;
    int j = tx & 31, e0 = tx >> 5;
#pragma unroll
    for (int i = 0; i < 16; i++) {
        int e = e0 + 8 * i;
        sm[e][j] = (e < E_) ? P[((size_t)bb * E_ + e) * 64 + j0 + j] : 0.f;
    }
    __syncthreads();
    int e = tx & 127, jg = tx >> 7;
#pragma unroll
    for (int p = 0; p < 16; p++) {
        int jj = jg + 2 * p;
        P2[((size_t)bb * 64 + j0 + jj) * 128 + e] = sm[e][jj];
    }
}

// ------ decoder attention pre-projection (once), writes (b,j,t) layout -----
__global__ void darnn_hproj(const float* __restrict__ hexp,
                            const float* __restrict__ W1dT,
                            const float* __restrict__ b1d,
                            float* __restrict__ Hproj2) {
    int row0 = blockIdx.x * 16;          // 16 (b,t) rows; same b (16 | 64)
    int b = row0 >> 6, t0 = row0 & 63;
    int tx = threadIdx.x;
    int j = tx & 127;
    int rs = tx >> 7;
    __shared__ float hs[16][129];
    __shared__ float outs[16][133];
#pragma unroll
    for (int i = 0; i < 8; i++) {
        int r = rs + 2 * i;
        hs[r][j] = hexp[((size_t)row0 + r) * H_ + j];
    }
    __syncthreads();
    float acc[8];
#pragma unroll
    for (int i = 0; i < 8; i++) acc[i] = b1d[j];
    for (int k = 0; k < 128; k++) {
        float w = W1dT[(256 + k) * 128 + j];
#pragma unroll
        for (int i = 0; i < 8; i++) acc[i] += hs[rs + 2 * i][k] * w;
    }
#pragma unroll
    for (int i = 0; i < 8; i++) outs[rs + 2 * i][j] = acc[i];
    __syncthreads();
    int t = tx & 15, jp = tx >> 4;       // 16 j per pass
#pragma unroll
    for (int p = 0; p < 8; p++) {
        int jj = jp + 16 * p;
        Hproj2[((size_t)b * 128 + jj) * 64 + t0 + t] = outs[t][jj];
    }
}

// -------------------------- encoder attention step --------------------------
__global__ void darnn_enc_attn(const float* __restrict__ input,
                               const float* __restrict__ h1, const float* __restrict__ c1,
                               const float* __restrict__ W1T,
                               const float* __restrict__ W2,
                               const float* __restrict__ b2,
                               const float* __restrict__ P2,
                               float* __restrict__ xs, int t) {
    int b = blockIdx.x;
    int tx = threadIdx.x;
    __shared__ float h1s[128], c1s[128], hvec[64], hvecc[64], W2s[64], red[128];
    h1s[tx] = h1[b * H_ + tx];
    c1s[tx] = c1[b * H_ + tx];
    if (tx < 64) W2s[tx] = W2[tx];
    __syncthreads();
    if (tx < 64) {
        float acc = 0.f;
#pragma unroll 8
        for (int h = 0; h < 128; h++) acc += h1s[h] * W1T[h * 64 + tx];
        hvec[tx] = acc;
    } else {
        int j = tx - 64;
        float acc = 0.f;
#pragma unroll 8
        for (int h = 0; h < 128; h++) acc += c1s[h] * W1T[(128 + h) * 64 + j];
        hvecc[j] = acc;
    }
    __syncthreads();
    if (tx < 64) hvec[tx] += hvecc[tx];
    __syncthreads();
    float lg = -3.0e38f;
    if (tx < E_) {
        const float* Pr = P2 + (size_t)b * 64 * 128 + tx;  // + j*128, coalesced over tx
        float acc = b2[0];
#pragma unroll 8
        for (int j = 0; j < 64; j++)
            acc += tanh_fma(Pr[j * 128] + hvec[j]) * W2s[j];
        lg = acc;
    }
    red[tx] = lg;
    __syncthreads();
    for (int s = 64; s > 0; s >>= 1) { if (tx < s) red[tx] = fmaxf(red[tx], red[tx + s]); __syncthreads(); }
    float m = red[0];
    __syncthreads();
    float ex = (tx < E_) ? __expf(lg - m) : 0.f;
    red[tx] = ex;
    __syncthreads();
    for (int s = 64; s > 0; s >>= 1) { if (tx < s) red[tx] += red[tx + s]; __syncthreads(); }
    float inv = 1.0f / red[0];
    if (tx < E_)
        xs[b * E_ + tx] = input[((size_t)b * T_ + t) * I_ + 1 + tx] * ex * inv;
}

// -------------------------- decoder attention step --------------------------
__global__ void darnn_dec_attn(const float* __restrict__ input,
                               const float* __restrict__ h1, const float* __restrict__ c1,
                               const float* __restrict__ W1dT,
                               const float* __restrict__ W2d,
                               const float* __restrict__ b2d,
                               const float* __restrict__ Hproj2,
                               const float* __restrict__ hexp,
                               const float* __restrict__ decinW,
                               const float* __restrict__ decinB,
                               float* __restrict__ din,
                               float* __restrict__ partial, int t) {
    int b = blockIdx.x;
    int tx = threadIdx.x;
    __shared__ float h1s[128], c1s[128], hvec[128], W2s[128], a_s[64], red[128];
    h1s[tx] = h1[b * H_ + tx];
    c1s[tx] = c1[b * H_ + tx];
    W2s[tx] = W2d[tx];
    __syncthreads();
    {
        float acc = 0.f;
#pragma unroll 8
        for (int h = 0; h < 128; h++)
            acc += h1s[h] * W1dT[h * 128 + tx] + c1s[h] * W1dT[(128 + h) * 128 + tx];
        hvec[tx] = acc;
    }
    __syncthreads();
    float lg = -3.0e38f;
    if (tx < T_) {
        const float* Pr = Hproj2 + (size_t)b * 128 * 64 + tx;  // + j*64, coalesced over tx
        float acc = b2d[0];
#pragma unroll 8
        for (int j = 0; j < 128; j++)
            acc += tanh_fma(Pr[j * 64] + hvec[j]) * W2s[j];
        lg = acc;
    }
    red[tx] = lg;
    __syncthreads();
    for (int s = 64; s > 0; s >>= 1) { if (tx < s) red[tx] = fmaxf(red[tx], red[tx + s]); __syncthreads(); }
    float m = red[0];
    __syncthreads();
    float ex = (tx < T_) ? __expf(lg - m) : 0.f;
    red[tx] = ex;
    __syncthreads();
    for (int s = 64; s > 0; s >>= 1) { if (tx < s) red[tx] += red[tx + s]; __syncthreads(); }
    float inv = 1.0f / red[0];
    if (tx < T_) a_s[tx] = ex * inv;
    __syncthreads();
    float p = 0.f;
#pragma unroll 8
    for (int tt = 0; tt < T_; tt++)
        p += a_s[tt] * hexp[((size_t)b * T_ + tt) * H_ + tx];
    partial[b * H_ + tx] = p;
    red[tx] = p * decinW[tx];
    __syncthreads();
    for (int s = 64; s > 0; s >>= 1) { if (tx < s) red[tx] += red[tx + s]; __syncthreads(); }
    if (tx == 0)
        din[b] = red[0] + decinW[128] * input[((size_t)b * T_ + t) * I_ + 0] + decinB[0];
}

// ------------------------------ fused LSTM cell -----------------------------
// Tile: 16 batches x 128 gate-rows per block, grid (32,4). 128 threads.
// Thread: 4 batches x 1 h x 4 gates (2 B LDS per FMA).
__global__ void darnn_lstm_cell(const float* __restrict__ X, int Kx,
                                const float* __restrict__ Wih,
                                const float* __restrict__ Hp,
                                const float* __restrict__ Whh,
                                const float* __restrict__ bih,
                                const float* __restrict__ bhh,
                                const float* __restrict__ Cp,
                                float* __restrict__ Hout,
                                float* __restrict__ Cout,
                                float* __restrict__ Hcopy, int hstride) {
    const int b0 = blockIdx.x * 16;
    const int h0 = blockIdx.y * 32;
    const int tx = threadIdx.x;
    const int bq = tx & 3;        // batch group (x4)
    const int hl = tx >> 2;       // 0..31 h-lane
    const int lane = tx & 31;
    const int wr = tx >> 5;       // warp id 0..3

    __shared__ float As[32][17];   // [k][b]
    __shared__ float Bs[32][133];  // [k][row]

    float acc[4][4];               // [bi][g]
#pragma unroll
    for (int i = 0; i < 4; i++)
#pragma unroll
        for (int g = 0; g < 4; g++) acc[i][g] = 0.f;

    for (int phase = 0; phase < 2; phase++) {
        const float* Ag = phase ? Hp : X;
        const float* Bg = phase ? Whh : Wih;
        const int K = phase ? H_ : Kx;
        const int ntiles = (K + 31) >> 5;
        for (int kt = 0; kt < ntiles; kt++) {
            const int kb = kt << 5;
            const bool ok = (kb + lane) < K;
            {
#pragma unroll
                for (int i = 0; i < 4; i++) {
                    int bb = wr + 4 * i;
                    As[lane][bb] = ok ? Ag[(size_t)(b0 + bb) * K + kb + lane] : 0.f;
                }
            }
            {
#pragma unroll
                for (int i = 0; i < 32; i++) {
                    int r = wr + 4 * i;
                    int g = r >> 5, hh = r & 31;
                    int row = g * H_ + h0 + hh;
                    Bs[lane][r] = ok ? Bg[(size_t)row * K + kb + lane] : 0.f;
                }
            }
            __syncthreads();
#pragma unroll
            for (int k = 0; k < 32; k++) {
                float a0 = As[k][bq * 4 + 0];
                float a1 = As[k][bq * 4 + 1];
                float a2 = As[k][bq * 4 + 2];
                float a3 = As[k][bq * 4 + 3];
#pragma unroll
                for (int g = 0; g < 4; g++) {
                    float w = Bs[k][g * 32 + hl];
                    acc[0][g] += a0 * w;
                    acc[1][g] += a1 * w;
                    acc[2][g] += a2 * w;
                    acc[3][g] += a3 * w;
                }
            }
            __syncthreads();
        }
    }
    const int h = h0 + hl;
    const float bi0 = bih[h]          + bhh[h];
    const float bf  = bih[H_ + h]     + bhh[H_ + h];
    const float bg  = bih[2*H_ + h]   + bhh[2*H_ + h];
    const float bo  = bih[3*H_ + h]   + bhh[3*H_ + h];
#pragma unroll
    for (int bi = 0; bi < 4; bi++) {
        int b = b0 + bq * 4 + bi;
        float gi = acc[bi][0] + bi0;
        float gf = acc[bi][1] + bf;
        float gg = acc[bi][2] + bg;
        float go = acc[bi][3] + bo;
        float cp = Cp[b * H_ + h];
        float c2 = sig_fma(gf) * cp + sig_fma(gi) * tanh_fma(gg);
        float h2 = sig_fma(go) * tanh_fma(c2);
        Cout[b * H_ + h] = c2;
        Hout[b * H_ + h] = h2;
        if (Hcopy) Hcopy[(size_t)b * hstride + h] = h2;
    }
}

// ------------------------------- final output -------------------------------
__global__ void darnn_final(const float* __restrict__ h1f,
                            const float* __restrict__ partial,
                            const float* __restrict__ projW,
                            const float* __restrict__ projB,
                            float* __restrict__ out) {
    int b = blockIdx.x * blockDim.x + threadIdx.x;
    if (b < B_) {
        float acc = projB[0];
#pragma unroll 8
        for (int h = 0; h < H_; h++)
            acc += h1f[b * H_ + h] * projW[h] + partial[b * H_ + h] * projW[H_ + h];
        out[b] = acc;
    }
}

// --------------------------------- launcher ---------------------------------
extern "C" void kernel_launch(void* const* d_in, const int* in_sizes, int n_in,
                              void* d_out, int out_size) {
    const float* input    = (const float*)d_in[0];
    const float* eWih0    = (const float*)d_in[1];
    const float* eWhh0    = (const float*)d_in[2];
    const float* ebih0    = (const float*)d_in[3];
    const float* ebhh0    = (const float*)d_in[4];
    const float* eWih1    = (const float*)d_in[5];
    const float* eWhh1    = (const float*)d_in[6];
    const float* ebih1    = (const float*)d_in[7];
    const float* ebhh1    = (const float*)d_in[8];
    const float* dWih0    = (const float*)d_in[9];
    const float* dWhh0    = (const float*)d_in[10];
    const float* dbih0    = (const float*)d_in[11];
    const float* dbhh0    = (const float*)d_in[12];
    const float* dWih1    = (const float*)d_in[13];
    const float* dWhh1    = (const float*)d_in[14];
    const float* dbih1    = (const float*)d_in[15];
    const float* dbhh1    = (const float*)d_in[16];
    const float* attnW1   = (const float*)d_in[17];
    const float* attnB1   = (const float*)d_in[18];
    const float* attnW2   = (const float*)d_in[19];
    const float* attnB2   = (const float*)d_in[20];
    const float* attndW1  = (const float*)d_in[21];
    const float* attndB1  = (const float*)d_in[22];
    const float* attndW2  = (const float*)d_in[23];
    const float* attndB2  = (const float*)d_in[24];
    const float* decinW   = (const float*)d_in[25];
    const float* decinB   = (const float*)d_in[26];
    const float* projW    = (const float*)d_in[27];
    const float* projB    = (const float*)d_in[28];
    (void)in_sizes; (void)n_in; (void)out_size;

    float *st, *P, *P2, *hexp, *Hproj2, *W1Te, *W1Td, *xs, *din, *part;
    cudaGetSymbolAddress((void**)&st,     g_state);
    cudaGetSymbolAddress((void**)&P,      g_P);
    cudaGetSymbolAddress((void**)&P2,     g_P2);
    cudaGetSymbolAddress((void**)&hexp,   g_hexp);
    cudaGetSymbolAddress((void**)&Hproj2, g_Hproj2);
    cudaGetSymbolAddress((void**)&W1Te,   g_W1Te);
    cudaGetSymbolAddress((void**)&W1Td,   g_W1Td);
    cudaGetSymbolAddress((void**)&xs,     g_xs);
    cudaGetSymbolAddress((void**)&din,    g_din);
    cudaGetSymbolAddress((void**)&part,   g_partial);

    float* h0[2] = { st + 0 * SN, st + 1 * SN };
    float* c0[2] = { st + 2 * SN, st + 3 * SN };
    float* h1[2] = { st + 4 * SN, st + 5 * SN };
    float* c1[2] = { st + 6 * SN, st + 7 * SN };

    dim3 cellGrid(32, 4);

    darnn_prep<<<256, 256>>>(attnW1, attndW1, W1Te, W1Td, h0[0], c0[0], h1[0], c1[0]);
    darnn_penc<<<(B_ * E_) / 4, 256>>>(input, W1Te, attnB1, P);
    darnn_ptrans<<<B_ * 2, 256>>>(P, P2);

    for (int t = 0; t < T_; t++) {
        int p = t & 1, q = p ^ 1;
        darnn_enc_attn<<<B_, 128>>>(input, h1[p], c1[p], W1Te, attnW2, attnB2, P2, xs, t);
        darnn_lstm_cell<<<cellGrid, 128>>>(xs, E_, eWih0, h0[p], eWhh0, ebih0, ebhh0,
                                           c0[p], h0[q], c0[q], nullptr, 0);
        darnn_lstm_cell<<<cellGrid, 128>>>(h0[q], H_, eWih1, h1[p], eWhh1, ebih1, ebhh1,
                                           c1[p], h1[q], c1[q], hexp + (size_t)t * H_, T_ * H_);
    }

    darnn_hproj<<<(B_ * T_) / 16, 256>>>(hexp, W1Td, attndB1, Hproj2);
    darnn_zero_states<<<256, 256>>>(h0[0], c0[0], h1[0], c1[0]);

    for (int t = 0; t < T_; t++) {
        int p = t & 1, q = p ^ 1;
        darnn_dec_attn<<<B_, 128>>>(input, h1[p], c1[p], W1Td, attndW2, attndB2,
                                    Hproj2, hexp, decinW, decinB, din, part, t);
        darnn_lstm_cell<<<cellGrid, 128>>>(din, 1, dWih0, h0[p], dWhh0, dbih0, dbhh0,
                                           c0[p], h0[q], c0[q], nullptr, 0);
        darnn_lstm_cell<<<cellGrid, 128>>>(h0[q], H_, dWih1, h1[p], dWhh1, dbih1, dbhh1,
                                           c1[p], h1[q], c1[q], nullptr, 0);
    }

    darnn_final<<<4, 128>>>(h1[0], part, projW, projB, (float*)d_out);
}

// round 11
// speedup vs baseline: 1.3150x; 1.1241x over previous
#include <cuda_runtime.h>
#include <cstddef>
#include <cstdint>

// ---------------------------------------------------------------------------
// DA-RNN: B=512, T=64, I=128, H=128, E=127
// Round 10: 512-thread attention kernels (parallel j-split) to fix the
// latency-bound 21%-occupancy attention identified by ncu; float4 A-tile in
// the LSTM cell to drop LDS issue below the crossbar limit.
// ---------------------------------------------------------------------------

#define B_  512
#define T_  64
#define I_  128
#define H_  128
#define E_  127
#define SN  (B_*H_)   // 65536

// ------------------------- device scratch (static) -------------------------
__device__ float g_state[8 * SN];
__device__ float g_P[(size_t)B_ * E_ * T_];      // enc pre-proj (b,e,j)
__device__ float g_P2[(size_t)B_ * 64 * 128];    // enc pre-proj (b,j,e)
__device__ float g_hexp[(size_t)B_ * T_ * H_];   // (b,t,h)
__device__ float g_Hproj2[(size_t)B_ * 128 * 64];// dec pre-proj (b,j,t)
__device__ float g_W1Te[320 * 64];
__device__ float g_W1Td[384 * 128];
__device__ float g_xs[B_ * E_];
__device__ float g_din[B_];
__device__ float g_partial[B_ * H_];

// ------------------------------ math helpers -------------------------------
__device__ __forceinline__ float rcp_fast(float q) {
    float r = __uint_as_float(0x7EF311C3u - __float_as_uint(q));
    r = r * fmaf(-q, r, 2.0f);
    r = r * fmaf(-q, r, 2.0f);
    r = r * fmaf(-q, r, 2.0f);
    return r;
}
__device__ __forceinline__ float tanh_fma(float x) {
    const float kClamp = 7.90531110763549805f;
    x = fminf(fmaxf(x, -kClamp), kClamp);
    float x2 = x * x;
    float p = -2.76076847742355e-16f;
    p = fmaf(p, x2, 2.00018790482477e-13f);
    p = fmaf(p, x2, -8.60467152213735e-11f);
    p = fmaf(p, x2, 5.12229709037114e-08f);
    p = fmaf(p, x2, 1.48572235717979e-05f);
    p = fmaf(p, x2, 6.37261928875436e-04f);
    p = fmaf(p, x2, 4.89352455891786e-03f);
    p = x * p;
    float q = 1.19825839466702e-06f;
    q = fmaf(q, x2, 1.18534705686654e-04f);
    q = fmaf(q, x2, 2.26843463243900e-03f);
    q = fmaf(q, x2, 4.89352518554385e-03f);
    return p * rcp_fast(q);
}
__device__ __forceinline__ float sig_fma(float x) {
    return fmaf(tanh_fma(0.5f * x), 0.5f, 0.5f);
}

// ------------------------- prep: W transposes + zero -----------------------
__global__ void darnn_prep(const float* __restrict__ aW1, const float* __restrict__ adW1,
                           float* __restrict__ W1Te, float* __restrict__ W1Td,
                           float* h0, float* c0, float* h1, float* c1) {
    int i = blockIdx.x * blockDim.x + threadIdx.x;
    if (i < 64 * 320) { int r = i / 320, c = i % 320; W1Te[c * 64 + r] = aW1[i]; }
    if (i < 128 * 384) { int r = i / 384, c = i % 384; W1Td[c * 128 + r] = adW1[i]; }
    if (i < SN) { h0[i] = 0.f; c0[i] = 0.f; h1[i] = 0.f; c1[i] = 0.f; }
}

__global__ void darnn_zero_states(float* h0, float* c0, float* h1, float* c1) {
    int i = blockIdx.x * blockDim.x + threadIdx.x;
    if (i < SN) { h0[i] = 0.f; c0[i] = 0.f; h1[i] = 0.f; c1[i] = 0.f; }
}

// ------------------ encoder attention pre-projection (once) ----------------
__global__ void darnn_penc(const float* __restrict__ input,
                           const float* __restrict__ W1T,
                           const float* __restrict__ b1,
                           float* __restrict__ P) {
    int row0 = blockIdx.x * 4;
    int tx = threadIdx.x;
    int j = tx & 63;
    int r = tx >> 6;
    int row = row0 + r;
    int b = row / E_;
    int e = row % E_;
    __shared__ float xsm[4][65];
    xsm[r][j] = input[((size_t)b * T_ + j) * I_ + 1 + e];
    __syncthreads();
    float acc = b1[j];
#pragma unroll 8
    for (int k = 0; k < 64; k++)
        acc += xsm[r][k] * W1T[(256 + k) * 64 + j];
    P[(size_t)row * 64 + j] = acc;
}

// -------- transpose P (b,e,j) -> P2 (b,j,e) --------------------------------
__global__ void darnn_ptrans(const float* __restrict__ P, float* __restrict__ P2) {
    int bb = blockIdx.x >> 1;
    int j0 = (blockIdx.x & 1) * 32;
    __shared__ float sm[128][33];
    int tx = threadIdx.x;
    int j = tx & 31, e0 = tx >> 5;
#pragma unroll
    for (int i = 0; i < 16; i++) {
        int e = e0 + 8 * i;
        sm[e][j] = (e < E_) ? P[((size_t)bb * E_ + e) * 64 + j0 + j] : 0.f;
    }
    __syncthreads();
    int e = tx & 127, jg = tx >> 7;
#pragma unroll
    for (int p = 0; p < 16; p++) {
        int jj = jg + 2 * p;
        P2[((size_t)bb * 64 + j0 + jj) * 128 + e] = sm[e][jj];
    }
}

// ------ decoder attention pre-projection (once), writes (b,j,t) layout -----
__global__ void darnn_hproj(const float* __restrict__ hexp,
                            const float* __restrict__ W1dT,
                            const float* __restrict__ b1d,
                            float* __restrict__ Hproj2) {
    int row0 = blockIdx.x * 16;
    int b = row0 >> 6, t0 = row0 & 63;
    int tx = threadIdx.x;
    int j = tx & 127;
    int rs = tx >> 7;
    __shared__ float hs[16][129];
    __shared__ float outs[16][133];
#pragma unroll
    for (int i = 0; i < 8; i++) {
        int r = rs + 2 * i;
        hs[r][j] = hexp[((size_t)row0 + r) * H_ + j];
    }
    __syncthreads();
    float acc[8];
#pragma unroll
    for (int i = 0; i < 8; i++) acc[i] = b1d[j];
    for (int k = 0; k < 128; k++) {
        float w = W1dT[(256 + k) * 128 + j];
#pragma unroll
        for (int i = 0; i < 8; i++) acc[i] += hs[rs + 2 * i][k] * w;
    }
#pragma unroll
    for (int i = 0; i < 8; i++) outs[rs + 2 * i][j] = acc[i];
    __syncthreads();
    int t = tx & 15, jp = tx >> 4;
#pragma unroll
    for (int p = 0; p < 8; p++) {
        int jj = jp + 16 * p;
        Hproj2[((size_t)b * 128 + jj) * 64 + t0 + t] = outs[t][jj];
    }
}

// --------------------- encoder attention step (512 thr) ---------------------
__global__ __launch_bounds__(512)
void darnn_enc_attn(const float* __restrict__ input,
                    const float* __restrict__ h1, const float* __restrict__ c1,
                    const float* __restrict__ W1T,
                    const float* __restrict__ W2,
                    const float* __restrict__ b2,
                    const float* __restrict__ P2,
                    float* __restrict__ xs, int t) {
    int b = blockIdx.x;
    int tx = threadIdx.x;
    __shared__ float h1s[128], c1s[128], W2s[64], hvJ[64];
    __shared__ float hpart[8][64];
    __shared__ float part[4][128];
    __shared__ float lgs[128], red[128];
    if (tx < 128) { h1s[tx] = h1[b * H_ + tx]; c1s[tx] = c1[b * H_ + tx]; }
    else if (tx < 192) W2s[tx - 128] = W2[tx - 128];
    __syncthreads();
    // hvec[j] = sum_h h1[h]*W1T[h,j] + c1[h]*W1T[128+h,j], split 8 ways over h
    {
        int j = tx & 63, pg = tx >> 6;
        int hlo = pg * 16;
        float a = 0.f;
#pragma unroll
        for (int i = 0; i < 16; i++) {
            int h = hlo + i;
            a += h1s[h] * W1T[h * 64 + j] + c1s[h] * W1T[(128 + h) * 64 + j];
        }
        hpart[pg][j] = a;
    }
    __syncthreads();
    if (tx < 64) {
        float a = 0.f;
#pragma unroll
        for (int p = 0; p < 8; p++) a += hpart[p][tx];
        hvJ[tx] = a;
    }
    __syncthreads();
    // logits: e = tx&127, quarter q over j
    {
        int e = tx & 127, q = tx >> 7;
        const float* Pr = P2 + (size_t)b * 64 * 128 + e;
        float acc = (q == 0) ? b2[0] : 0.f;
#pragma unroll
        for (int jj = 0; jj < 16; jj++) {
            int j = q * 16 + jj;
            acc += tanh_fma(Pr[j * 128] + hvJ[j]) * W2s[j];
        }
        part[q][e] = acc;
    }
    __syncthreads();
    if (tx < 128) {
        float lg = part[0][tx] + part[1][tx] + part[2][tx] + part[3][tx];
        if (tx >= E_) lg = -3.0e38f;
        lgs[tx] = lg;
        red[tx] = lg;
    }
    __syncthreads();
    for (int s = 64; s > 0; s >>= 1) { if (tx < s) red[tx] = fmaxf(red[tx], red[tx + s]); __syncthreads(); }
    float m = red[0];
    __syncthreads();
    float ex = 0.f;
    if (tx < 128) {
        ex = (tx < E_) ? __expf(lgs[tx] - m) : 0.f;
        red[tx] = ex;
    }
    __syncthreads();
    for (int s = 64; s > 0; s >>= 1) { if (tx < s) red[tx] += red[tx + s]; __syncthreads(); }
    float inv = 1.0f / red[0];
    if (tx < E_)
        xs[b * E_ + tx] = input[((size_t)b * T_ + t) * I_ + 1 + tx] * ex * inv;
}

// --------------------- decoder attention step (512 thr) ---------------------
__global__ __launch_bounds__(512)
void darnn_dec_attn(const float* __restrict__ input,
                    const float* __restrict__ h1, const float* __restrict__ c1,
                    const float* __restrict__ W1dT,
                    const float* __restrict__ W2d,
                    const float* __restrict__ b2d,
                    const float* __restrict__ Hproj2,
                    const float* __restrict__ hexp,
                    const float* __restrict__ decinW,
                    const float* __restrict__ decinB,
                    float* __restrict__ din,
                    float* __restrict__ partial, int t) {
    int b = blockIdx.x;
    int tx = threadIdx.x;
    __shared__ float h1s[128], c1s[128], W2s[128], hvJ[128];
    __shared__ float hpart[4][128];
    __shared__ float part2[8][64];
    __shared__ float cpart[4][128];
    __shared__ float a_s[64], lgs[64], red[128];
    if (tx < 128) { h1s[tx] = h1[b * H_ + tx]; c1s[tx] = c1[b * H_ + tx]; }
    else if (tx < 256) W2s[tx - 128] = W2d[tx - 128];
    __syncthreads();
    // hvec[j], split 4 ways over h
    {
        int j = tx & 127, pg = tx >> 7;
        int hlo = pg * 32;
        float a = 0.f;
#pragma unroll
        for (int i = 0; i < 32; i++) {
            int h = hlo + i;
            a += h1s[h] * W1dT[h * 128 + j] + c1s[h] * W1dT[(128 + h) * 128 + j];
        }
        hpart[pg][j] = a;
    }
    __syncthreads();
    if (tx < 128)
        hvJ[tx] = hpart[0][tx] + hpart[1][tx] + hpart[2][tx] + hpart[3][tx];
    __syncthreads();
    // logits: t' = tx&63, oc = tx>>6 splits j 8 ways
    {
        int tt = tx & 63, oc = tx >> 6;
        const float* Pr = Hproj2 + (size_t)b * 128 * 64 + tt;
        float acc = (oc == 0) ? b2d[0] : 0.f;
#pragma unroll
        for (int jj = 0; jj < 16; jj++) {
            int j = oc * 16 + jj;
            acc += tanh_fma(Pr[j * 64] + hvJ[j]) * W2s[j];
        }
        part2[oc][tt] = acc;
    }
    __syncthreads();
    if (tx < 64) {
        float lg = 0.f;
#pragma unroll
        for (int p = 0; p < 8; p++) lg += part2[p][tx];
        lgs[tx] = lg;
        red[tx] = lg;
    }
    __syncthreads();
    for (int s = 32; s > 0; s >>= 1) { if (tx < s) red[tx] = fmaxf(red[tx], red[tx + s]); __syncthreads(); }
    float m = red[0];
    __syncthreads();
    if (tx < 64) red[tx] = __expf(lgs[tx] - m);
    __syncthreads();
    float ex = (tx < 64) ? red[tx] : 0.f;
    for (int s = 32; s > 0; s >>= 1) { if (tx < s) red[tx] += red[tx + s]; __syncthreads(); }
    if (tx < 64) a_s[tx] = ex / red[0];
    __syncthreads();
    // context: h = tx&127, tg = tx>>7 splits t 4 ways
    {
        int h = tx & 127, tg = tx >> 7;
        float p = 0.f;
#pragma unroll
        for (int i = 0; i < 16; i++) {
            int tt = tg * 16 + i;
            p += a_s[tt] * hexp[((size_t)b * T_ + tt) * H_ + h];
        }
        cpart[tg][h] = p;
    }
    __syncthreads();
    if (tx < 128) {
        float p = cpart[0][tx] + cpart[1][tx] + cpart[2][tx] + cpart[3][tx];
        partial[b * H_ + tx] = p;
        red[tx] = p * decinW[tx];
    }
    __syncthreads();
    for (int s = 64; s > 0; s >>= 1) { if (tx < s) red[tx] += red[tx + s]; __syncthreads(); }
    if (tx == 0)
        din[b] = red[0] + decinW[128] * input[((size_t)b * T_ + t) * I_ + 0] + decinB[0];
}

// ------------------------------ fused LSTM cell -----------------------------
// 16 batches x 128 gate-rows per block, grid (32,4), 128 threads.
// A-operand read as one LDS.128 (As padded to 20 floats/row, 16B-aligned).
__global__ void darnn_lstm_cell(const float* __restrict__ X, int Kx,
                                const float* __restrict__ Wih,
                                const float* __restrict__ Hp,
                                const float* __restrict__ Whh,
                                const float* __restrict__ bih,
                                const float* __restrict__ bhh,
                                const float* __restrict__ Cp,
                                float* __restrict__ Hout,
                                float* __restrict__ Cout,
                                float* __restrict__ Hcopy, int hstride) {
    const int b0 = blockIdx.x * 16;
    const int h0 = blockIdx.y * 32;
    const int tx = threadIdx.x;
    const int bq = tx & 3;
    const int hl = tx >> 2;
    const int lane = tx & 31;
    const int wr = tx >> 5;

    __shared__ float As[32][20];   // [k][b], padded; rows 16B-aligned
    __shared__ float Bs[32][133];  // [k][row]

    float acc[4][4];
#pragma unroll
    for (int i = 0; i < 4; i++)
#pragma unroll
        for (int g = 0; g < 4; g++) acc[i][g] = 0.f;

    for (int phase = 0; phase < 2; phase++) {
        const float* Ag = phase ? Hp : X;
        const float* Bg = phase ? Whh : Wih;
        const int K = phase ? H_ : Kx;
        const int ntiles = (K + 31) >> 5;
        for (int kt = 0; kt < ntiles; kt++) {
            const int kb = kt << 5;
            const bool ok = (kb + lane) < K;
#pragma unroll
            for (int i = 0; i < 4; i++) {
                int bb = wr + 4 * i;
                As[lane][bb] = ok ? Ag[(size_t)(b0 + bb) * K + kb + lane] : 0.f;
            }
#pragma unroll
            for (int i = 0; i < 32; i++) {
                int r = wr + 4 * i;
                int g = r >> 5, hh = r & 31;
                int row = g * H_ + h0 + hh;
                Bs[lane][r] = ok ? Bg[(size_t)row * K + kb + lane] : 0.f;
            }
            __syncthreads();
#pragma unroll
            for (int k = 0; k < 32; k++) {
                float4 av = *(const float4*)&As[k][bq * 4];
#pragma unroll
                for (int g = 0; g < 4; g++) {
                    float w = Bs[k][g * 32 + hl];
                    acc[0][g] += av.x * w;
                    acc[1][g] += av.y * w;
                    acc[2][g] += av.z * w;
                    acc[3][g] += av.w * w;
                }
            }
            __syncthreads();
        }
    }
    const int h = h0 + hl;
    const float bi0 = bih[h]          + bhh[h];
    const float bf  = bih[H_ + h]     + bhh[H_ + h];
    const float bg  = bih[2*H_ + h]   + bhh[2*H_ + h];
    const float bo  = bih[3*H_ + h]   + bhh[3*H_ + h];
#pragma unroll
    for (int bi = 0; bi < 4; bi++) {
        int b = b0 + bq * 4 + bi;
        float gi = acc[bi][0] + bi0;
        float gf = acc[bi][1] + bf;
        float gg = acc[bi][2] + bg;
        float go = acc[bi][3] + bo;
        float cp = Cp[b * H_ + h];
        float c2 = sig_fma(gf) * cp + sig_fma(gi) * tanh_fma(gg);
        float h2 = sig_fma(go) * tanh_fma(c2);
        Cout[b * H_ + h] = c2;
        Hout[b * H_ + h] = h2;
        if (Hcopy) Hcopy[(size_t)b * hstride + h] = h2;
    }
}

// ------------------------------- final output -------------------------------
__global__ void darnn_final(const float* __restrict__ h1f,
                            const float* __restrict__ partial,
                            const float* __restrict__ projW,
                            const float* __restrict__ projB,
                            float* __restrict__ out) {
    int b = blockIdx.x * blockDim.x + threadIdx.x;
    if (b < B_) {
        float acc = projB[0];
#pragma unroll 8
        for (int h = 0; h < H_; h++)
            acc += h1f[b * H_ + h] * projW[h] + partial[b * H_ + h] * projW[H_ + h];
        out[b] = acc;
    }
}

// --------------------------------- launcher ---------------------------------
extern "C" void kernel_launch(void* const* d_in, const int* in_sizes, int n_in,
                              void* d_out, int out_size) {
    const float* input    = (const float*)d_in[0];
    const float* eWih0    = (const float*)d_in[1];
    const float* eWhh0    = (const float*)d_in[2];
    const float* ebih0    = (const float*)d_in[3];
    const float* ebhh0    = (const float*)d_in[4];
    const float* eWih1    = (const float*)d_in[5];
    const float* eWhh1    = (const float*)d_in[6];
    const float* ebih1    = (const float*)d_in[7];
    const float* ebhh1    = (const float*)d_in[8];
    const float* dWih0    = (const float*)d_in[9];
    const float* dWhh0    = (const float*)d_in[10];
    const float* dbih0    = (const float*)d_in[11];
    const float* dbhh0    = (const float*)d_in[12];
    const float* dWih1    = (const float*)d_in[13];
    const float* dWhh1    = (const float*)d_in[14];
    const float* dbih1    = (const float*)d_in[15];
    const float* dbhh1    = (const float*)d_in[16];
    const float* attnW1   = (const float*)d_in[17];
    const float* attnB1   = (const float*)d_in[18];
    const float* attnW2   = (const float*)d_in[19];
    const float* attnB2   = (const float*)d_in[20];
    const float* attndW1  = (const float*)d_in[21];
    const float* attndB1  = (const float*)d_in[22];
    const float* attndW2  = (const float*)d_in[23];
    const float* attndB2  = (const float*)d_in[24];
    const float* decinW   = (const float*)d_in[25];
    const float* decinB   = (const float*)d_in[26];
    const float* projW    = (const float*)d_in[27];
    const float* projB    = (const float*)d_in[28];
    (void)in_sizes; (void)n_in; (void)out_size;

    float *st, *P, *P2, *hexp, *Hproj2, *W1Te, *W1Td, *xs, *din, *part;
    cudaGetSymbolAddress((void**)&st,     g_state);
    cudaGetSymbolAddress((void**)&P,      g_P);
    cudaGetSymbolAddress((void**)&P2,     g_P2);
    cudaGetSymbolAddress((void**)&hexp,   g_hexp);
    cudaGetSymbolAddress((void**)&Hproj2, g_Hproj2);
    cudaGetSymbolAddress((void**)&W1Te,   g_W1Te);
    cudaGetSymbolAddress((void**)&W1Td,   g_W1Td);
    cudaGetSymbolAddress((void**)&xs,     g_xs);
    cudaGetSymbolAddress((void**)&din,    g_din);
    cudaGetSymbolAddress((void**)&part,   g_partial);

    float* h0[2] = { st + 0 * SN, st + 1 * SN };
    float* c0[2] = { st + 2 * SN, st + 3 * SN };
    float* h1[2] = { st + 4 * SN, st + 5 * SN };
    float* c1[2] = { st + 6 * SN, st + 7 * SN };

    dim3 cellGrid(32, 4);

    darnn_prep<<<256, 256>>>(attnW1, attndW1, W1Te, W1Td, h0[0], c0[0], h1[0], c1[0]);
    darnn_penc<<<(B_ * E_) / 4, 256>>>(input, W1Te, attnB1, P);
    darnn_ptrans<<<B_ * 2, 256>>>(P, P2);

    for (int t = 0; t < T_; t++) {
        int p = t & 1, q = p ^ 1;
        darnn_enc_attn<<<B_, 512>>>(input, h1[p], c1[p], W1Te, attnW2, attnB2, P2, xs, t);
        darnn_lstm_cell<<<cellGrid, 128>>>(xs, E_, eWih0, h0[p], eWhh0, ebih0, ebhh0,
                                           c0[p], h0[q], c0[q], nullptr, 0);
        darnn_lstm_cell<<<cellGrid, 128>>>(h0[q], H_, eWih1, h1[p], eWhh1, ebih1, ebhh1,
                                           c1[p], h1[q], c1[q], hexp + (size_t)t * H_, T_ * H_);
    }

    darnn_hproj<<<(B_ * T_) / 16, 256>>>(hexp, W1Td, attndB1, Hproj2);
    darnn_zero_states<<<256, 256>>>(h0[0], c0[0], h1[0], c1[0]);

    for (int t = 0; t < T_; t++) {
        int p = t & 1, q = p ^ 1;
        darnn_dec_attn<<<B_, 512>>>(input, h1[p], c1[p], W1Td, attndW2, attndB2,
                                    Hproj2, hexp, decinW, decinB, din, part, t);
        darnn_lstm_cell<<<cellGrid, 128>>>(din, 1, dWih0, h0[p], dWhh0, dbih0, dbhh0,
                                           c0[p], h0[q], c0[q], nullptr, 0);
        darnn_lstm_cell<<<cellGrid, 128>>>(h0[q], H_, dWih1, h1[p], dWhh1, dbih1, dbhh1,
                                           c1[p], h1[q], c1[q], nullptr, 0);
    }

    darnn_final<<<4, 128>>>(h1[0], part, projW, projB, (float*)d_out);
}

// round 13
// speedup vs baseline: 1.3277x; 1.0097x over previous
#include <cuda_runtime.h>
#include <cstddef>
#include <cstdint>

// ---------------------------------------------------------------------------
// DA-RNN: B=512, T=64, I=128, H=128, E=127
// Round 12: same theory as R11 (L2 evict_last on re-read streams), corrected
// PTX encoding: createpolicy + ld.global.nc.L2::cache_hint (scalar-legal).
// ---------------------------------------------------------------------------

#define B_  512
#define T_  64
#define I_  128
#define H_  128
#define E_  127
#define SN  (B_*H_)   // 65536

// ------------------------- device scratch (static) -------------------------
__device__ float g_state[8 * SN];
__device__ float g_P[(size_t)B_ * E_ * T_];      // enc pre-proj (b,e,j)
__device__ float g_P2[(size_t)B_ * 64 * 128];    // enc pre-proj (b,j,e)
__device__ float g_hexp[(size_t)B_ * T_ * H_];   // (b,t,h)
__device__ float g_Hproj2[(size_t)B_ * 128 * 64];// dec pre-proj (b,j,t)
__device__ float g_W1Te[320 * 64];
__device__ float g_W1Td[384 * 128];
__device__ float g_xs[B_ * E_];
__device__ float g_din[B_];
__device__ float g_partial[B_ * H_];

// ------------------------------ math helpers -------------------------------
__device__ __forceinline__ float rcp_fast(float q) {
    float r = __uint_as_float(0x7EF311C3u - __float_as_uint(q));
    r = r * fmaf(-q, r, 2.0f);
    r = r * fmaf(-q, r, 2.0f);
    r = r * fmaf(-q, r, 2.0f);
    return r;
}
__device__ __forceinline__ float tanh_fma(float x) {
    const float kClamp = 7.90531110763549805f;
    x = fminf(fmaxf(x, -kClamp), kClamp);
    float x2 = x * x;
    float p = -2.76076847742355e-16f;
    p = fmaf(p, x2, 2.00018790482477e-13f);
    p = fmaf(p, x2, -8.60467152213735e-11f);
    p = fmaf(p, x2, 5.12229709037114e-08f);
    p = fmaf(p, x2, 1.48572235717979e-05f);
    p = fmaf(p, x2, 6.37261928875436e-04f);
    p = fmaf(p, x2, 4.89352455891786e-03f);
    p = x * p;
    float q = 1.19825839466702e-06f;
    q = fmaf(q, x2, 1.18534705686654e-04f);
    q = fmaf(q, x2, 2.26843463243900e-03f);
    q = fmaf(q, x2, 4.89352518554385e-03f);
    return p * rcp_fast(q);
}
__device__ __forceinline__ float sig_fma(float x) {
    return fmaf(tanh_fma(0.5f * x), 0.5f, 0.5f);
}
// L2 evict_last read via cache-hint policy (scalar-legal encoding)
__device__ __forceinline__ float ldg_last(const float* p) {
    float v;
    asm("{\n\t"
        ".reg .b64 pol;\n\t"
        "createpolicy.fractional.L2::evict_last.b64 pol, 1.0;\n\t"
        "ld.global.nc.L2::cache_hint.f32 %0, [%1], pol;\n\t"
        "}" : "=f"(v) : "l"(p));
    return v;
}

// ------------------------- prep: W transposes + zero -----------------------
__global__ void darnn_prep(const float* __restrict__ aW1, const float* __restrict__ adW1,
                           float* __restrict__ W1Te, float* __restrict__ W1Td,
                           float* h0, float* c0, float* h1, float* c1) {
    int i = blockIdx.x * blockDim.x + threadIdx.x;
    if (i < 64 * 320) { int r = i / 320, c = i % 320; W1Te[c * 64 + r] = aW1[i]; }
    if (i < 128 * 384) { int r = i / 384, c = i % 384; W1Td[c * 128 + r] = adW1[i]; }
    if (i < SN) { h0[i] = 0.f; c0[i] = 0.f; h1[i] = 0.f; c1[i] = 0.f; }
}

__global__ void darnn_zero_states(float* h0, float* c0, float* h1, float* c1) {
    int i = blockIdx.x * blockDim.x + threadIdx.x;
    if (i < SN) { h0[i] = 0.f; c0[i] = 0.f; h1[i] = 0.f; c1[i] = 0.f; }
}

// ------------------ encoder attention pre-projection (once) ----------------
__global__ void darnn_penc(const float* __restrict__ input,
                           const float* __restrict__ W1T,
                           const float* __restrict__ b1,
                           float* __restrict__ P) {
    int row0 = blockIdx.x * 4;
    int tx = threadIdx.x;
    int j = tx & 63;
    int r = tx >> 6;
    int row = row0 + r;
    int b = row / E_;
    int e = row % E_;
    __shared__ float xsm[4][65];
    xsm[r][j] = input[((size_t)b * T_ + j) * I_ + 1 + e];
    __syncthreads();
    float acc = b1[j];
#pragma unroll 8
    for (int k = 0; k < 64; k++)
        acc += xsm[r][k] * W1T[(256 + k) * 64 + j];
    P[(size_t)row * 64 + j] = acc;
}

// -------- transpose P (b,e,j) -> P2 (b,j,e) --------------------------------
__global__ void darnn_ptrans(const float* __restrict__ P, float* __restrict__ P2) {
    int bb = blockIdx.x >> 1;
    int j0 = (blockIdx.x & 1) * 32;
    __shared__ float sm[128][33];
    int tx = threadIdx.x;
    int j = tx & 31, e0 = tx >> 5;
#pragma unroll
    for (int i = 0; i < 16; i++) {
        int e = e0 + 8 * i;
        sm[e][j] = (e < E_) ? P[((size_t)bb * E_ + e) * 64 + j0 + j] : 0.f;
    }
    __syncthreads();
    int e = tx & 127, jg = tx >> 7;
#pragma unroll
    for (int p = 0; p < 16; p++) {
        int jj = jg + 2 * p;
        P2[((size_t)bb * 64 + j0 + jj) * 128 + e] = sm[e][jj];
    }
}

// ------ decoder attention pre-projection (once), writes (b,j,t) layout -----
__global__ void darnn_hproj(const float* __restrict__ hexp,
                            const float* __restrict__ W1dT,
                            const float* __restrict__ b1d,
                            float* __restrict__ Hproj2) {
    int row0 = blockIdx.x * 16;
    int b = row0 >> 6, t0 = row0 & 63;
    int tx = threadIdx.x;
    int j = tx & 127;
    int rs = tx >> 7;
    __shared__ float hs[16][129];
    __shared__ float outs[16][133];
#pragma unroll
    for (int i = 0; i < 8; i++) {
        int r = rs + 2 * i;
        hs[r][j] = hexp[((size_t)row0 + r) * H_ + j];
    }
    __syncthreads();
    float acc[8];
#pragma unroll
    for (int i = 0; i < 8; i++) acc[i] = b1d[j];
    for (int k = 0; k < 128; k++) {
        float w = W1dT[(256 + k) * 128 + j];
#pragma unroll
        for (int i = 0; i < 8; i++) acc[i] += hs[rs + 2 * i][k] * w;
    }
#pragma unroll
    for (int i = 0; i < 8; i++) outs[rs + 2 * i][j] = acc[i];
    __syncthreads();
    int t = tx & 15, jp = tx >> 4;
#pragma unroll
    for (int p = 0; p < 8; p++) {
        int jj = jp + 16 * p;
        Hproj2[((size_t)b * 128 + jj) * 64 + t0 + t] = outs[t][jj];
    }
}

// --------------------- encoder attention step (512 thr) ---------------------
__global__ __launch_bounds__(512)
void darnn_enc_attn(const float* __restrict__ input,
                    const float* __restrict__ h1, const float* __restrict__ c1,
                    const float* __restrict__ W1T,
                    const float* __restrict__ W2,
                    const float* __restrict__ b2,
                    const float* __restrict__ P2,
                    float* __restrict__ xs, int t) {
    int b = blockIdx.x;
    int tx = threadIdx.x;
    __shared__ float h1s[128], c1s[128], W2s[64], hvJ[64];
    __shared__ float hpart[8][64];
    __shared__ float part[4][128];
    __shared__ float lgs[128], red[128];
    if (tx < 128) { h1s[tx] = h1[b * H_ + tx]; c1s[tx] = c1[b * H_ + tx]; }
    else if (tx < 192) W2s[tx - 128] = W2[tx - 128];
    __syncthreads();
    {
        int j = tx & 63, pg = tx >> 6;
        int hlo = pg * 16;
        float a = 0.f;
#pragma unroll
        for (int i = 0; i < 16; i++) {
            int h = hlo + i;
            a += h1s[h] * W1T[h * 64 + j] + c1s[h] * W1T[(128 + h) * 64 + j];
        }
        hpart[pg][j] = a;
    }
    __syncthreads();
    if (tx < 64) {
        float a = 0.f;
#pragma unroll
        for (int p = 0; p < 8; p++) a += hpart[p][tx];
        hvJ[tx] = a;
    }
    __syncthreads();
    {
        int e = tx & 127, q = tx >> 7;
        const float* Pr = P2 + (size_t)b * 64 * 128 + e;
        float acc = (q == 0) ? b2[0] : 0.f;
#pragma unroll
        for (int jj = 0; jj < 16; jj++) {
            int j = q * 16 + jj;
            acc += tanh_fma(ldg_last(Pr + j * 128) + hvJ[j]) * W2s[j];
        }
        part[q][e] = acc;
    }
    __syncthreads();
    if (tx < 128) {
        float lg = part[0][tx] + part[1][tx] + part[2][tx] + part[3][tx];
        if (tx >= E_) lg = -3.0e38f;
        lgs[tx] = lg;
        red[tx] = lg;
    }
    __syncthreads();
    for (int s = 64; s > 0; s >>= 1) { if (tx < s) red[tx] = fmaxf(red[tx], red[tx + s]); __syncthreads(); }
    float m = red[0];
    __syncthreads();
    float ex = 0.f;
    if (tx < 128) {
        ex = (tx < E_) ? __expf(lgs[tx] - m) : 0.f;
        red[tx] = ex;
    }
    __syncthreads();
    for (int s = 64; s > 0; s >>= 1) { if (tx < s) red[tx] += red[tx + s]; __syncthreads(); }
    float inv = 1.0f / red[0];
    if (tx < E_)
        xs[b * E_ + tx] = input[((size_t)b * T_ + t) * I_ + 1 + tx] * ex * inv;
}

// --------------------- decoder attention step (512 thr) ---------------------
__global__ __launch_bounds__(512)
void darnn_dec_attn(const float* __restrict__ input,
                    const float* __restrict__ h1, const float* __restrict__ c1,
                    const float* __restrict__ W1dT,
                    const float* __restrict__ W2d,
                    const float* __restrict__ b2d,
                    const float* __restrict__ Hproj2,
                    const float* __restrict__ hexp,
                    const float* __restrict__ decinW,
                    const float* __restrict__ decinB,
                    float* __restrict__ din,
                    float* __restrict__ partial, int t) {
    int b = blockIdx.x;
    int tx = threadIdx.x;
    __shared__ float h1s[128], c1s[128], W2s[128], hvJ[128];
    __shared__ float hpart[4][128];
    __shared__ float part2[8][64];
    __shared__ float cpart[4][128];
    __shared__ float a_s[64], lgs[64], red[128];
    if (tx < 128) { h1s[tx] = h1[b * H_ + tx]; c1s[tx] = c1[b * H_ + tx]; }
    else if (tx < 256) W2s[tx - 128] = W2d[tx - 128];
    __syncthreads();
    {
        int j = tx & 127, pg = tx >> 7;
        int hlo = pg * 32;
        float a = 0.f;
#pragma unroll
        for (int i = 0; i < 32; i++) {
            int h = hlo + i;
            a += h1s[h] * W1dT[h * 128 + j] + c1s[h] * W1dT[(128 + h) * 128 + j];
        }
        hpart[pg][j] = a;
    }
    __syncthreads();
    if (tx < 128)
        hvJ[tx] = hpart[0][tx] + hpart[1][tx] + hpart[2][tx] + hpart[3][tx];
    __syncthreads();
    {
        int tt = tx & 63, oc = tx >> 6;
        const float* Pr = Hproj2 + (size_t)b * 128 * 64 + tt;
        float acc = (oc == 0) ? b2d[0] : 0.f;
#pragma unroll
        for (int jj = 0; jj < 16; jj++) {
            int j = oc * 16 + jj;
            acc += tanh_fma(ldg_last(Pr + j * 64) + hvJ[j]) * W2s[j];
        }
        part2[oc][tt] = acc;
    }
    __syncthreads();
    if (tx < 64) {
        float lg = 0.f;
#pragma unroll
        for (int p = 0; p < 8; p++) lg += part2[p][tx];
        lgs[tx] = lg;
        red[tx] = lg;
    }
    __syncthreads();
    for (int s = 32; s > 0; s >>= 1) { if (tx < s) red[tx] = fmaxf(red[tx], red[tx + s]); __syncthreads(); }
    float m = red[0];
    __syncthreads();
    if (tx < 64) red[tx] = __expf(lgs[tx] - m);
    __syncthreads();
    float ex = (tx < 64) ? red[tx] : 0.f;
    for (int s = 32; s > 0; s >>= 1) { if (tx < s) red[tx] += red[tx + s]; __syncthreads(); }
    if (tx < 64) a_s[tx] = ex / red[0];
    __syncthreads();
    {
        int h = tx & 127, tg = tx >> 7;
        float p = 0.f;
#pragma unroll
        for (int i = 0; i < 16; i++) {
            int tt = tg * 16 + i;
            p += a_s[tt] * ldg_last(hexp + ((size_t)b * T_ + tt) * H_ + h);
        }
        cpart[tg][h] = p;
    }
    __syncthreads();
    if (tx < 128) {
        float p = cpart[0][tx] + cpart[1][tx] + cpart[2][tx] + cpart[3][tx];
        partial[b * H_ + tx] = p;
        red[tx] = p * decinW[tx];
    }
    __syncthreads();
    for (int s = 64; s > 0; s >>= 1) { if (tx < s) red[tx] += red[tx + s]; __syncthreads(); }
    if (tx == 0)
        din[b] = red[0] + decinW[128] * input[((size_t)b * T_ + t) * I_ + 0] + decinB[0];
}

// ------------------------------ fused LSTM cell -----------------------------
__global__ void darnn_lstm_cell(const float* __restrict__ X, int Kx,
                                const float* __restrict__ Wih,
                                const float* __restrict__ Hp,
                                const float* __restrict__ Whh,
                                const float* __restrict__ bih,
                                const float* __restrict__ bhh,
                                const float* __restrict__ Cp,
                                float* __restrict__ Hout,
                                float* __restrict__ Cout,
                                float* __restrict__ Hcopy, int hstride) {
    const int b0 = blockIdx.x * 16;
    const int h0 = blockIdx.y * 32;
    const int tx = threadIdx.x;
    const int bq = tx & 3;
    const int hl = tx >> 2;
    const int lane = tx & 31;
    const int wr = tx >> 5;

    __shared__ float As[32][20];
    __shared__ float Bs[32][133];

    float acc[4][4];
#pragma unroll
    for (int i = 0; i < 4; i++)
#pragma unroll
        for (int g = 0; g < 4; g++) acc[i][g] = 0.f;

    for (int phase = 0; phase < 2; phase++) {
        const float* Ag = phase ? Hp : X;
        const float* Bg = phase ? Whh : Wih;
        const int K = phase ? H_ : Kx;
        const int ntiles = (K + 31) >> 5;
        for (int kt = 0; kt < ntiles; kt++) {
            const int kb = kt << 5;
            const bool ok = (kb + lane) < K;
#pragma unroll
            for (int i = 0; i < 4; i++) {
                int bb = wr + 4 * i;
                As[lane][bb] = ok ? Ag[(size_t)(b0 + bb) * K + kb + lane] : 0.f;
            }
#pragma unroll
            for (int i = 0; i < 32; i++) {
                int r = wr + 4 * i;
                int g = r >> 5, hh = r & 31;
                int row = g * H_ + h0 + hh;
                Bs[lane][r] = ok ? Bg[(size_t)row * K + kb + lane] : 0.f;
            }
            __syncthreads();
#pragma unroll
            for (int k = 0; k < 32; k++) {
                float4 av = *(const float4*)&As[k][bq * 4];
#pragma unroll
                for (int g = 0; g < 4; g++) {
                    float w = Bs[k][g * 32 + hl];
                    acc[0][g] += av.x * w;
                    acc[1][g] += av.y * w;
                    acc[2][g] += av.z * w;
                    acc[3][g] += av.w * w;
                }
            }
            __syncthreads();
        }
    }
    const int h = h0 + hl;
    const float bi0 = bih[h]          + bhh[h];
    const float bf  = bih[H_ + h]     + bhh[H_ + h];
    const float bg  = bih[2*H_ + h]   + bhh[2*H_ + h];
    const float bo  = bih[3*H_ + h]   + bhh[3*H_ + h];
#pragma unroll
    for (int bi = 0; bi < 4; bi++) {
        int b = b0 + bq * 4 + bi;
        float gi = acc[bi][0] + bi0;
        float gf = acc[bi][1] + bf;
        float gg = acc[bi][2] + bg;
        float go = acc[bi][3] + bo;
        float cp = Cp[b * H_ + h];
        float c2 = sig_fma(gf) * cp + sig_fma(gi) * tanh_fma(gg);
        float h2 = sig_fma(go) * tanh_fma(c2);
        Cout[b * H_ + h] = c2;
        Hout[b * H_ + h] = h2;
        if (Hcopy) Hcopy[(size_t)b * hstride + h] = h2;
    }
}

// ------------------------------- final output -------------------------------
__global__ void darnn_final(const float* __restrict__ h1f,
                            const float* __restrict__ partial,
                            const float* __restrict__ projW,
                            const float* __restrict__ projB,
                            float* __restrict__ out) {
    int b = blockIdx.x * blockDim.x + threadIdx.x;
    if (b < B_) {
        float acc = projB[0];
#pragma unroll 8
        for (int h = 0; h < H_; h++)
            acc += h1f[b * H_ + h] * projW[h] + partial[b * H_ + h] * projW[H_ + h];
        out[b] = acc;
    }
}

// --------------------------------- launcher ---------------------------------
extern "C" void kernel_launch(void* const* d_in, const int* in_sizes, int n_in,
                              void* d_out, int out_size) {
    const float* input    = (const float*)d_in[0];
    const float* eWih0    = (const float*)d_in[1];
    const float* eWhh0    = (const float*)d_in[2];
    const float* ebih0    = (const float*)d_in[3];
    const float* ebhh0    = (const float*)d_in[4];
    const float* eWih1    = (const float*)d_in[5];
    const float* eWhh1    = (const float*)d_in[6];
    const float* ebih1    = (const float*)d_in[7];
    const float* ebhh1    = (const float*)d_in[8];
    const float* dWih0    = (const float*)d_in[9];
    const float* dWhh0    = (const float*)d_in[10];
    const float* dbih0    = (const float*)d_in[11];
    const float* dbhh0    = (const float*)d_in[12];
    const float* dWih1    = (const float*)d_in[13];
    const float* dWhh1    = (const float*)d_in[14];
    const float* dbih1    = (const float*)d_in[15];
    const float* dbhh1    = (const float*)d_in[16];
    const float* attnW1   = (const float*)d_in[17];
    const float* attnB1   = (const float*)d_in[18];
    const float* attnW2   = (const float*)d_in[19];
    const float* attnB2   = (const float*)d_in[20];
    const float* attndW1  = (const float*)d_in[21];
    const float* attndB1  = (const float*)d_in[22];
    const float* attndW2  = (const float*)d_in[23];
    const float* attndB2  = (const float*)d_in[24];
    const float* decinW   = (const float*)d_in[25];
    const float* decinB   = (const float*)d_in[26];
    const float* projW    = (const float*)d_in[27];
    const float* projB    = (const float*)d_in[28];
    (void)in_sizes; (void)n_in; (void)out_size;

    float *st, *P, *P2, *hexp, *Hproj2, *W1Te, *W1Td, *xs, *din, *part;
    cudaGetSymbolAddress((void**)&st,     g_state);
    cudaGetSymbolAddress((void**)&P,      g_P);
    cudaGetSymbolAddress((void**)&P2,     g_P2);
    cudaGetSymbolAddress((void**)&hexp,   g_hexp);
    cudaGetSymbolAddress((void**)&Hproj2, g_Hproj2);
    cudaGetSymbolAddress((void**)&W1Te,   g_W1Te);
    cudaGetSymbolAddress((void**)&W1Td,   g_W1Td);
    cudaGetSymbolAddress((void**)&xs,     g_xs);
    cudaGetSymbolAddress((void**)&din,    g_din);
    cudaGetSymbolAddress((void**)&part,   g_partial);

    float* h0[2] = { st + 0 * SN, st + 1 * SN };
    float* c0[2] = { st + 2 * SN, st + 3 * SN };
    float* h1[2] = { st + 4 * SN, st + 5 * SN };
    float* c1[2] = { st + 6 * SN, st + 7 * SN };

    dim3 cellGrid(32, 4);

    darnn_prep<<<256, 256>>>(attnW1, attndW1, W1Te, W1Td, h0[0], c0[0], h1[0], c1[0]);
    darnn_penc<<<(B_ * E_) / 4, 256>>>(input, W1Te, attnB1, P);
    darnn_ptrans<<<B_ * 2, 256>>>(P, P2);

    for (int t = 0; t < T_; t++) {
        int p = t & 1, q = p ^ 1;
        darnn_enc_attn<<<B_, 512>>>(input, h1[p], c1[p], W1Te, attnW2, attnB2, P2, xs, t);
        darnn_lstm_cell<<<cellGrid, 128>>>(xs, E_, eWih0, h0[p], eWhh0, ebih0, ebhh0,
                                           c0[p], h0[q], c0[q], nullptr, 0);
        darnn_lstm_cell<<<cellGrid, 128>>>(h0[q], H_, eWih1, h1[p], eWhh1, ebih1, ebhh1,
                                           c1[p], h1[q], c1[q], hexp + (size_t)t * H_, T_ * H_);
    }

    darnn_hproj<<<(B_ * T_) / 16, 256>>>(hexp, W1Td, attndB1, Hproj2);
    darnn_zero_states<<<256, 256>>>(h0[0], c0[0], h1[0], c1[0]);

    for (int t = 0; t < T_; t++) {
        int p = t & 1, q = p ^ 1;
        darnn_dec_attn<<<B_, 512>>>(input, h1[p], c1[p], W1Td, attndW2, attndB2,
                                    Hproj2, hexp, decinW, decinB, din, part, t);
        darnn_lstm_cell<<<cellGrid, 128>>>(din, 1, dWih0, h0[p], dWhh0, dbih0, dbhh0,
                                           c0[p], h0[q], c0[q], nullptr, 0);
        darnn_lstm_cell<<<cellGrid, 128>>>(h0[q], H_, dWih1, h1[p], dWhh1, dbih1, dbhh1,
                                           c1[p], h1[q], c1[q], nullptr, 0);
    }

    darnn_final<<<4, 128>>>(h1[0], part, projW, projB, (float*)d_out);
}